// round 3
// baseline (speedup 1.0000x reference)
#include <cuda_runtime.h>
#include <math.h>

#define THREADS 96
typedef unsigned long long ull;

// ---------------- f32x2 packed helpers (Blackwell) ----------------
__device__ __forceinline__ ull pack2(float lo, float hi) {
    ull r; asm("mov.b64 %0, {%1, %2};" : "=l"(r) : "f"(lo), "f"(hi)); return r;
}
__device__ __forceinline__ void unpack2(ull v, float& lo, float& hi) {
    asm("mov.b64 {%0, %1}, %2;" : "=f"(lo), "=f"(hi) : "l"(v));
}
__device__ __forceinline__ ull ffma2(ull a, ull b, ull c) {
    ull d; asm("fma.rn.f32x2 %0, %1, %2, %3;" : "=l"(d) : "l"(a), "l"(b), "l"(c)); return d;
}

// ---------------- 3x3 helpers ----------------
__device__ __forceinline__ void mm3(const float* a, const float* b, float* c) {
#pragma unroll
    for (int r = 0; r < 3; ++r)
#pragma unroll
        for (int k = 0; k < 3; ++k)
            c[r * 3 + k] = a[r * 3 + 0] * b[0 * 3 + k]
                         + a[r * 3 + 1] * b[1 * 3 + k]
                         + a[r * 3 + 2] * b[2 * 3 + k];
}
__device__ __forceinline__ float tr3(const float* a) { return a[0] + a[4] + a[8]; }
__device__ __forceinline__ float trAB(const float* a, const float* b) {
    float t = 0.f;
#pragma unroll
    for (int i = 0; i < 3; ++i)
#pragma unroll
        for (int k = 0; k < 3; ++k)
            t += a[i * 3 + k] * b[k * 3 + i];
    return t;
}
__device__ __forceinline__ void axpy9(float* acc, float g, const float* m) {
#pragma unroll
    for (int k = 0; k < 9; ++k) acc[k] += g * m[k];
}
__device__ __forceinline__ void axmy9(float* acc, float g, const float* m, const float* n) {
#pragma unroll
    for (int k = 0; k < 9; ++k) acc[k] += g * (m[k] - n[k]);
}

// -------------- stage KROWS x NPAD weight rows (N zero-padded) --------------
template <int KROWS, int NPAD, int NTRUE>
__device__ __forceinline__ void stage(const float* __restrict__ Wg,
                                      float* __restrict__ wbuf, int tid)
{
    for (int idx = tid; idx < KROWS * NPAD; idx += THREADS) {
        int i = idx / NPAD;
        int j = idx - i * NPAD;
        wbuf[idx] = (j < NTRUE) ? __ldg(Wg + i * NTRUE + j) : 0.f;
    }
}
template <int NPAD, int NTRUE>
__device__ __forceinline__ void stage_bias(const float* __restrict__ Bg,
                                           float* __restrict__ bbuf, int tid)
{
    for (int j = tid; j < NPAD; j += THREADS)
        bbuf[j] = (j < NTRUE) ? __ldg(Bg + j) : 0.f;
}

// -------------- init accumulators from staged bias --------------
template <int NPAIRS>
__device__ __forceinline__ void init_acc(const float* __restrict__ bbuf,
                                         ull* acc0, ull* acc1)
{
#pragma unroll
    for (int j = 0; j < NPAIRS; ++j) {
        float2 bv = reinterpret_cast<const float2*>(bbuf)[j];
        ull p = pack2(bv.x, bv.y);
        acc0[j] = p;
        acc1[j] = p;
    }
}

// -------------- GEMV chunk: KCHUNK rows, both elements, f32x2 --------------
template <int KCHUNK, int NPAIRS>
__device__ __forceinline__ void gemv_chunk(const float* __restrict__ wbuf,
                                           const float* __restrict__ actin,
                                           ull* acc0, ull* acc1, int tid)
{
#pragma unroll 2
    for (int i = 0; i < KCHUNK; ++i) {
        float x0 = actin[i * (2 * THREADS) + tid];
        float x1 = actin[i * (2 * THREADS) + THREADS + tid];
        ull xs0 = pack2(x0, x0);
        ull xs1 = pack2(x1, x1);
        const char* row = reinterpret_cast<const char*>(wbuf + i * (2 * NPAIRS));
#pragma unroll
        for (int j = 0; j < NPAIRS / 2; ++j) {
            ulonglong2 wv = reinterpret_cast<const ulonglong2*>(row)[j];
            acc0[2 * j]     = ffma2(xs0, wv.x, acc0[2 * j]);
            acc1[2 * j]     = ffma2(xs1, wv.x, acc1[2 * j]);
            acc0[2 * j + 1] = ffma2(xs0, wv.y, acc0[2 * j + 1]);
            acc1[2 * j + 1] = ffma2(xs1, wv.y, acc1[2 * j + 1]);
        }
        if (NPAIRS & 1) {
            ull wv = reinterpret_cast<const ull*>(row)[NPAIRS - 1];
            acc0[NPAIRS - 1] = ffma2(xs0, wv, acc0[NPAIRS - 1]);
            acc1[NPAIRS - 1] = ffma2(xs1, wv, acc1[NPAIRS - 1]);
        }
    }
}

// -------------- store accumulators (leaky relu) into act smem --------------
template <int NPAIRS, bool RELU>
__device__ __forceinline__ void store_act(const ull* acc0, const ull* acc1,
                                          float* __restrict__ act, int tid)
{
#pragma unroll
    for (int j = 0; j < NPAIRS; ++j) {
        float a, b, c, d;
        unpack2(acc0[j], a, b);
        unpack2(acc1[j], c, d);
        if (RELU) {
            a = fmaxf(a, 0.1f * a); b = fmaxf(b, 0.1f * b);
            c = fmaxf(c, 0.1f * c); d = fmaxf(d, 0.1f * d);
        }
        act[(2 * j) * (2 * THREADS) + tid] = a;
        act[(2 * j + 1) * (2 * THREADS) + tid] = b;
        act[(2 * j) * (2 * THREADS) + THREADS + tid] = c;
        act[(2 * j + 1) * (2 * THREADS) + THREADS + tid] = d;
    }
}

// -------------- epilogue per element --------------
__device__ __forceinline__ void finish_elem(const float* __restrict__ Sg,
                                            const float* __restrict__ Wg,
                                            const float* g, long b, long bb,
                                            int Btot, float* __restrict__ out)
{
    float s[9], w[9];
#pragma unroll
    for (int k = 0; k < 9; ++k) {
        s[k] = Sg[bb * 9 + k];
        w[k] = Wg[bb * 9 + k];
    }
    float raw[9];
#pragma unroll
    for (int k = 0; k < 9; ++k) raw[k] = 0.f;

    axpy9(raw, g[0], s);                       // T1
    float s2[9], w2[9];
    mm3(s, s, s2);
    mm3(w, w, w2);
    axpy9(raw, g[2], s2);                      // T3
    { float c = g[2] * tr3(s2) * (1.f / 3.f); raw[0] -= c; raw[4] -= c; raw[8] -= c; }
    axpy9(raw, g[3], w2);                      // T4
    { float c = g[3] * tr3(w2) * (1.f / 3.f); raw[0] -= c; raw[4] -= c; raw[8] -= c; }

    float sw[9], ws[9];
    mm3(s, w, sw);
    mm3(w, s, ws);
    axmy9(raw, g[1], sw, ws);                  // T2

    float tA[9], tB[9];
    mm3(ws, w2, tA); mm3(w2, sw, tB); axmy9(raw, g[6], tA, tB);  // T7
    mm3(sw, s2, tA); mm3(s2, ws, tB); axmy9(raw, g[7], tA, tB);  // T8

    float ws2[9], s2w[9];
    mm3(w, s2, ws2);
    mm3(s2, w, s2w);
    axmy9(raw, g[4], ws2, s2w);                // T5
    mm3(ws2, w2, tA); mm3(w2, s2w, tB); axmy9(raw, g[9], tA, tB); // T10

    mm3(w2, s, tA); mm3(s, w2, tB);            // T6
    axpy9(raw, g[5], tA); axpy9(raw, g[5], tB);
    { float c = g[5] * (2.f / 3.f) * tr3(tB); raw[0] -= c; raw[4] -= c; raw[8] -= c; }

    mm3(w2, s2, tA); mm3(s2, w2, tB);          // T9
    axpy9(raw, g[8], tA); axpy9(raw, g[8], tB);
    { float c = g[8] * (2.f / 3.f) * tr3(tB); raw[0] -= c; raw[4] -= c; raw[8] -= c; }

    float Q[9];
#pragma unroll
    for (int k = 0; k < 9; ++k) Q[k] = raw[k];
    {
        float c = (raw[0] + raw[4] + raw[8]) * (1.f / 3.f);
        Q[0] -= c; Q[4] -= c; Q[8] -= c;
    }
    float Qs[9];
#pragma unroll
    for (int r = 0; r < 3; ++r)
#pragma unroll
        for (int c = 0; c < 3; ++c)
            Qs[r * 3 + c] = 0.5f * (Q[r * 3 + c] + Q[c * 3 + r]);

    float ns = 0.f;
#pragma unroll
    for (int k = 0; k < 9; ++k) ns += Qs[k] * Qs[k];
    float invn = 1.0f / sqrtf(ns + 1e-16f);

    if (b < Btot) {
        float* outQ = out + b * 9;
        float* outR = out + (size_t)Btot * 9 + b * 9;
#pragma unroll
        for (int k = 0; k < 9; ++k) {
            outQ[k] = Qs[k] * invn;
            outR[k] = raw[k];
        }
    }
}

// smem: wbuf 100*52 (max 5200 floats), bbuf 104, act 100 * 2*THREADS
#define WBUF_FLOATS 5200
#define BBUF_FLOATS 104
#define ACT_FLOATS  (100 * 2 * THREADS)
#define SMEM_FLOATS (WBUF_FLOATS + BBUF_FLOATS + ACT_FLOATS)

__global__ void __launch_bounds__(THREADS, 2) tbnn_kernel(
    const float* __restrict__ Sg, const float* __restrict__ Wg,
    const float* __restrict__ W0, const float* __restrict__ B0,
    const float* __restrict__ W1, const float* __restrict__ B1,
    const float* __restrict__ W2, const float* __restrict__ B2,
    const float* __restrict__ W3, const float* __restrict__ B3,
    const float* __restrict__ W4, const float* __restrict__ B4,
    const float* __restrict__ W5, const float* __restrict__ B5,
    float* __restrict__ out, int Btot)
{
    extern __shared__ float smem[];
    float* wbuf = smem;                   // 16B aligned
    float* bbuf = wbuf + WBUF_FLOATS;
    float* act  = bbuf + BBUF_FLOATS;

    const int tid = threadIdx.x;
    const long base = (long)blockIdx.x * (2 * THREADS);
    const long b0 = base + tid;
    const long b1 = base + THREADS + tid;
    const long bb0 = (b0 < Btot) ? b0 : (long)Btot - 1;
    const long bb1 = (b1 < Btot) ? b1 : (long)Btot - 1;

    // ---- invariants for both elements ----
    float invA[5], invB[5];
#pragma unroll
    for (int e = 0; e < 2; ++e) {
        const long bb = e ? bb1 : bb0;
        float s[9], w[9];
#pragma unroll
        for (int k = 0; k < 9; ++k) {
            s[k] = Sg[bb * 9 + k];
            w[k] = Wg[bb * 9 + k];
        }
        float s2[9], w2[9];
        mm3(s, s, s2);
        mm3(w, w, w2);
        float* inv = e ? invB : invA;
        inv[0] = tr3(s2);
        inv[1] = tr3(w2);
        inv[2] = trAB(s2, s);
        inv[3] = trAB(w2, s);
        inv[4] = trAB(w2, s2);
    }

    // ================= layer 0: 5 -> 52 (true 50), x from regs =================
    stage<5, 52, 50>(W0, wbuf, tid);
    stage_bias<52, 50>(B0, bbuf, tid);
    __syncthreads();
    {
        ull acc0[26], acc1[26];
        init_acc<26>(bbuf, acc0, acc1);
#pragma unroll
        for (int i = 0; i < 5; ++i) {
            ull xs0 = pack2(invA[i], invA[i]);
            ull xs1 = pack2(invB[i], invB[i]);
            const ulonglong2* wr = reinterpret_cast<const ulonglong2*>(wbuf + i * 52);
#pragma unroll
            for (int j = 0; j < 13; ++j) {
                ulonglong2 wv = wr[j];
                acc0[2 * j]     = ffma2(xs0, wv.x, acc0[2 * j]);
                acc1[2 * j]     = ffma2(xs1, wv.x, acc1[2 * j]);
                acc0[2 * j + 1] = ffma2(xs0, wv.y, acc0[2 * j + 1]);
                acc1[2 * j + 1] = ffma2(xs1, wv.y, acc1[2 * j + 1]);
            }
        }
        __syncthreads();   // all done reading wbuf before restage
        store_act<26, true>(acc0, acc1, act, tid);
    }

    // ================= layer 1: 50 -> 100 =================
    stage<50, 100, 100>(W1, wbuf, tid);
    stage_bias<100, 100>(B1, bbuf, tid);
    __syncthreads();       // staging + act stores visible
    {
        ull acc0[50], acc1[50];
        init_acc<50>(bbuf, acc0, acc1);
        gemv_chunk<50, 50>(wbuf, act, acc0, acc1, tid);
        __syncthreads();   // reads of act/wbuf done before overwrite
        store_act<50, true>(acc0, acc1, act, tid);
    }

    // ================= layers 2,3: 100 -> 100 (K chunked 50+50) =================
    const float* Wbig[2] = { W2, W3 };
    const float* Bbig[2] = { B2, B3 };
#pragma unroll 1
    for (int L = 0; L < 2; ++L) {
        stage<50, 100, 100>(Wbig[L], wbuf, tid);
        stage_bias<100, 100>(Bbig[L], bbuf, tid);
        __syncthreads();
        ull acc0[50], acc1[50];
        init_acc<50>(bbuf, acc0, acc1);
        gemv_chunk<50, 50>(wbuf, act, acc0, acc1, tid);
        __syncthreads();
        stage<50, 100, 100>(Wbig[L] + 50 * 100, wbuf, tid);
        __syncthreads();
        gemv_chunk<50, 50>(wbuf, act + 50 * (2 * THREADS), acc0, acc1, tid);
        __syncthreads();
        store_act<50, true>(acc0, acc1, act, tid);
    }

    // ================= layer 4: 100 -> 52 (true 50) =================
    stage<100, 52, 50>(W4, wbuf, tid);
    stage_bias<52, 50>(B4, bbuf, tid);
    __syncthreads();
    {
        ull acc0[26], acc1[26];
        init_acc<26>(bbuf, acc0, acc1);
        gemv_chunk<100, 26>(wbuf, act, acc0, acc1, tid);
        __syncthreads();
        store_act<26, true>(acc0, acc1, act, tid);
    }

    // ================= layer 5: 50 -> 16 (true 10), keep in regs =================
    stage<50, 16, 10>(W5, wbuf, tid);
    stage_bias<16, 10>(B5, bbuf, tid);
    __syncthreads();
    float gA[10], gB[10];
    {
        ull acc0[8], acc1[8];
        init_acc<8>(bbuf, acc0, acc1);
        gemv_chunk<50, 8>(wbuf, act, acc0, acc1, tid);
#pragma unroll
        for (int j = 0; j < 5; ++j) {
            unpack2(acc0[j], gA[2 * j], gA[2 * j + 1]);
            unpack2(acc1[j], gB[2 * j], gB[2 * j + 1]);
        }
    }

    // ================= epilogue: both elements =================
    finish_elem(Sg, Wg, gA, b0, bb0, Btot, out);
    finish_elem(Sg, Wg, gB, b1, bb1, Btot, out);
}

extern "C" void kernel_launch(void* const* d_in, const int* in_sizes, int n_in,
                              void* d_out, int out_size)
{
    const float* s  = (const float*)d_in[0];
    const float* w  = (const float*)d_in[1];
    const float* W0 = (const float*)d_in[2];
    const float* B0 = (const float*)d_in[3];
    const float* W1 = (const float*)d_in[4];
    const float* B1 = (const float*)d_in[5];
    const float* W2 = (const float*)d_in[6];
    const float* B2 = (const float*)d_in[7];
    const float* W3 = (const float*)d_in[8];
    const float* B3 = (const float*)d_in[9];
    const float* W4 = (const float*)d_in[10];
    const float* B4 = (const float*)d_in[11];
    const float* W5 = (const float*)d_in[12];
    const float* B5 = (const float*)d_in[13];
    float* out = (float*)d_out;

    int Btot = in_sizes[0] / 9;
    int smem_bytes = SMEM_FLOATS * (int)sizeof(float);
    cudaFuncSetAttribute(tbnn_kernel, cudaFuncAttributeMaxDynamicSharedMemorySize, smem_bytes);

    int elems_per_block = 2 * THREADS;
    int blocks = (Btot + elems_per_block - 1) / elems_per_block;
    tbnn_kernel<<<blocks, THREADS, smem_bytes>>>(
        s, w, W0, B0, W1, B1, W2, B2, W3, B3, W4, B4, W5, B5, out, Btot);
}

// round 4
// speedup vs baseline: 1.0978x; 1.0978x over previous
#include <cuda_runtime.h>
#include <math.h>

#define THREADS 160
typedef unsigned long long ull;

// ---------------- f32x2 packed helpers (Blackwell) ----------------
__device__ __forceinline__ ull pack2(float lo, float hi) {
    ull r; asm("mov.b64 %0, {%1, %2};" : "=l"(r) : "f"(lo), "f"(hi)); return r;
}
__device__ __forceinline__ void unpack2(ull v, float& lo, float& hi) {
    asm("mov.b64 {%0, %1}, %2;" : "=f"(lo), "=f"(hi) : "l"(v));
}
__device__ __forceinline__ ull ffma2(ull a, ull b, ull c) {
    ull d; asm("fma.rn.f32x2 %0, %1, %2, %3;" : "=l"(d) : "l"(a), "l"(b), "l"(c)); return d;
}

// ---------------- 3x3 helpers ----------------
__device__ __forceinline__ void mm3(const float* a, const float* b, float* c) {
#pragma unroll
    for (int r = 0; r < 3; ++r)
#pragma unroll
        for (int k = 0; k < 3; ++k)
            c[r * 3 + k] = a[r * 3 + 0] * b[0 * 3 + k]
                         + a[r * 3 + 1] * b[1 * 3 + k]
                         + a[r * 3 + 2] * b[2 * 3 + k];
}
__device__ __forceinline__ float tr3(const float* a) { return a[0] + a[4] + a[8]; }
__device__ __forceinline__ float trAB(const float* a, const float* b) {
    float t = 0.f;
#pragma unroll
    for (int i = 0; i < 3; ++i)
#pragma unroll
        for (int k = 0; k < 3; ++k)
            t += a[i * 3 + k] * b[k * 3 + i];
    return t;
}
__device__ __forceinline__ void axpy9(float* acc, float g, const float* m) {
#pragma unroll
    for (int k = 0; k < 9; ++k) acc[k] += g * m[k];
}
__device__ __forceinline__ void axmy9(float* acc, float g, const float* m, const float* n) {
#pragma unroll
    for (int k = 0; k < 9; ++k) acc[k] += g * (m[k] - n[k]);
}

// -------------- stage KROWS x NPAD weight rows (N zero-padded) --------------
template <int KROWS, int NPAD, int NTRUE>
__device__ __forceinline__ void stage(const float* __restrict__ Wg,
                                      float* __restrict__ wbuf, int tid)
{
    for (int idx = tid; idx < KROWS * NPAD; idx += THREADS) {
        int i = idx / NPAD;
        int j = idx - i * NPAD;
        wbuf[idx] = (j < NTRUE) ? __ldg(Wg + i * NTRUE + j) : 0.f;
    }
}
template <int NPAD, int NTRUE>
__device__ __forceinline__ void stage_bias(const float* __restrict__ Bg,
                                           float* __restrict__ bbuf, int tid)
{
    for (int j = tid; j < NPAD; j += THREADS)
        bbuf[j] = (j < NTRUE) ? __ldg(Bg + j) : 0.f;
}

// -------------- init f32x2 accumulators from staged bias --------------
template <int NPAIRS>
__device__ __forceinline__ void init_acc(const float* __restrict__ bbuf, ull* acc)
{
#pragma unroll
    for (int j = 0; j < NPAIRS; ++j) {
        float2 bv = reinterpret_cast<const float2*>(bbuf)[j];
        acc[j] = pack2(bv.x, bv.y);
    }
}

// -------------- GEMV chunk: KCHUNK rows, 1 element/thread, f32x2 --------------
template <int KCHUNK, int NPAIRS>
__device__ __forceinline__ void gemv1(const float* __restrict__ wbuf,
                                      const float* __restrict__ actin,
                                      ull* acc, int tid)
{
#pragma unroll 2
    for (int i = 0; i < KCHUNK; ++i) {
        float x = actin[i * THREADS + tid];
        ull xs = pack2(x, x);
        const ulonglong2* wr = reinterpret_cast<const ulonglong2*>(wbuf + i * (2 * NPAIRS));
#pragma unroll
        for (int j = 0; j < NPAIRS / 2; ++j) {
            ulonglong2 wv = wr[j];
            acc[2 * j]     = ffma2(xs, wv.x, acc[2 * j]);
            acc[2 * j + 1] = ffma2(xs, wv.y, acc[2 * j + 1]);
        }
    }
}

// -------------- store accumulators (leaky relu) into act smem --------------
template <int NPAIRS, bool RELU>
__device__ __forceinline__ void store_act(const ull* acc, float* __restrict__ act, int tid)
{
#pragma unroll
    for (int j = 0; j < NPAIRS; ++j) {
        float a, b;
        unpack2(acc[j], a, b);
        if (RELU) {
            a = fmaxf(a, 0.1f * a);
            b = fmaxf(b, 0.1f * b);
        }
        act[(2 * j) * THREADS + tid] = a;
        act[(2 * j + 1) * THREADS + tid] = b;
    }
}

// -------------- epilogue per element --------------
__device__ __forceinline__ void finish_elem(const float* __restrict__ Sg,
                                            const float* __restrict__ Wg,
                                            const float* g, long b, long bb,
                                            int Btot, float* __restrict__ out)
{
    float s[9], w[9];
#pragma unroll
    for (int k = 0; k < 9; ++k) {
        s[k] = Sg[bb * 9 + k];
        w[k] = Wg[bb * 9 + k];
    }
    float raw[9];
#pragma unroll
    for (int k = 0; k < 9; ++k) raw[k] = 0.f;

    axpy9(raw, g[0], s);                       // T1
    float s2[9], w2[9];
    mm3(s, s, s2);
    mm3(w, w, w2);
    axpy9(raw, g[2], s2);                      // T3
    { float c = g[2] * tr3(s2) * (1.f / 3.f); raw[0] -= c; raw[4] -= c; raw[8] -= c; }
    axpy9(raw, g[3], w2);                      // T4
    { float c = g[3] * tr3(w2) * (1.f / 3.f); raw[0] -= c; raw[4] -= c; raw[8] -= c; }

    float sw[9], ws[9];
    mm3(s, w, sw);
    mm3(w, s, ws);
    axmy9(raw, g[1], sw, ws);                  // T2

    float tA[9], tB[9];
    mm3(ws, w2, tA); mm3(w2, sw, tB); axmy9(raw, g[6], tA, tB);  // T7
    mm3(sw, s2, tA); mm3(s2, ws, tB); axmy9(raw, g[7], tA, tB);  // T8

    float ws2[9], s2w[9];
    mm3(w, s2, ws2);
    mm3(s2, w, s2w);
    axmy9(raw, g[4], ws2, s2w);                // T5
    mm3(ws2, w2, tA); mm3(w2, s2w, tB); axmy9(raw, g[9], tA, tB); // T10

    mm3(w2, s, tA); mm3(s, w2, tB);            // T6
    axpy9(raw, g[5], tA); axpy9(raw, g[5], tB);
    { float c = g[5] * (2.f / 3.f) * tr3(tB); raw[0] -= c; raw[4] -= c; raw[8] -= c; }

    mm3(w2, s2, tA); mm3(s2, w2, tB);          // T9
    axpy9(raw, g[8], tA); axpy9(raw, g[8], tB);
    { float c = g[8] * (2.f / 3.f) * tr3(tB); raw[0] -= c; raw[4] -= c; raw[8] -= c; }

    float Q[9];
#pragma unroll
    for (int k = 0; k < 9; ++k) Q[k] = raw[k];
    {
        float c = (raw[0] + raw[4] + raw[8]) * (1.f / 3.f);
        Q[0] -= c; Q[4] -= c; Q[8] -= c;
    }
    float Qs[9];
#pragma unroll
    for (int r = 0; r < 3; ++r)
#pragma unroll
        for (int c = 0; c < 3; ++c)
            Qs[r * 3 + c] = 0.5f * (Q[r * 3 + c] + Q[c * 3 + r]);

    float ns = 0.f;
#pragma unroll
    for (int k = 0; k < 9; ++k) ns += Qs[k] * Qs[k];
    float invn = 1.0f / sqrtf(ns + 1e-16f);

    if (b < Btot) {
        float* outQ = out + b * 9;
        float* outR = out + (size_t)Btot * 9 + b * 9;
#pragma unroll
        for (int k = 0; k < 9; ++k) {
            outQ[k] = Qs[k] * invn;
            outR[k] = raw[k];
        }
    }
}

// smem: wbuf 50*104 floats, bbuf 104, act 104*THREADS
#define WBUF_FLOATS (50 * 104)
#define BBUF_FLOATS 104
#define ACT_FLOATS  (104 * THREADS)
#define SMEM_FLOATS (WBUF_FLOATS + BBUF_FLOATS + ACT_FLOATS)

__global__ void __launch_bounds__(THREADS, 2) tbnn_kernel(
    const float* __restrict__ Sg, const float* __restrict__ Wg,
    const float* __restrict__ W0, const float* __restrict__ B0,
    const float* __restrict__ W1, const float* __restrict__ B1,
    const float* __restrict__ W2, const float* __restrict__ B2,
    const float* __restrict__ W3, const float* __restrict__ B3,
    const float* __restrict__ W4, const float* __restrict__ B4,
    const float* __restrict__ W5, const float* __restrict__ B5,
    float* __restrict__ out, int Btot)
{
    extern __shared__ float smem[];
    float* wbuf = smem;
    float* bbuf = wbuf + WBUF_FLOATS;
    float* act  = bbuf + BBUF_FLOATS;

    const int tid = threadIdx.x;
    const long b = (long)blockIdx.x * THREADS + tid;
    const long bb = (b < Btot) ? b : (long)Btot - 1;

    // ---- invariants ----
    float inv[5];
    {
        float s[9], w[9];
#pragma unroll
        for (int k = 0; k < 9; ++k) {
            s[k] = Sg[bb * 9 + k];
            w[k] = Wg[bb * 9 + k];
        }
        float s2[9], w2[9];
        mm3(s, s, s2);
        mm3(w, w, w2);
        inv[0] = tr3(s2);
        inv[1] = tr3(w2);
        inv[2] = trAB(s2, s);
        inv[3] = trAB(w2, s);
        inv[4] = trAB(w2, s2);
    }

    // ================= layer 0: 5 -> 52pad (true 50), x from regs =================
    stage<5, 52, 50>(W0, wbuf, tid);
    stage_bias<52, 50>(B0, bbuf, tid);
    __syncthreads();
    {
        ull acc[26];
        init_acc<26>(bbuf, acc);
#pragma unroll
        for (int i = 0; i < 5; ++i) {
            ull xs = pack2(inv[i], inv[i]);
            const ulonglong2* wr = reinterpret_cast<const ulonglong2*>(wbuf + i * 52);
#pragma unroll
            for (int j = 0; j < 13; ++j) {
                ulonglong2 wv = wr[j];
                acc[2 * j]     = ffma2(xs, wv.x, acc[2 * j]);
                acc[2 * j + 1] = ffma2(xs, wv.y, acc[2 * j + 1]);
            }
        }
        __syncthreads();   // wbuf reads done before restage
        store_act<26, true>(acc, act, tid);
    }

    // ================= layer 1: 50 -> 104pad (true 100) =================
    stage<50, 104, 100>(W1, wbuf, tid);
    stage_bias<104, 100>(B1, bbuf, tid);
    __syncthreads();       // staging + act stores visible
    {
        ull acc[52];
        init_acc<52>(bbuf, acc);
        gemv1<50, 52>(wbuf, act, acc, tid);
        __syncthreads();   // act/wbuf reads done before overwrite
        store_act<52, true>(acc, act, tid);
    }

    // ================= layers 2,3: 100 -> 104pad (K chunked 50+50) =================
    const float* Wbig[2] = { W2, W3 };
    const float* Bbig[2] = { B2, B3 };
#pragma unroll 1
    for (int L = 0; L < 2; ++L) {
        stage<50, 104, 100>(Wbig[L], wbuf, tid);
        stage_bias<104, 100>(Bbig[L], bbuf, tid);
        __syncthreads();
        ull acc[52];
        init_acc<52>(bbuf, acc);
        gemv1<50, 52>(wbuf, act, acc, tid);
        __syncthreads();
        stage<50, 104, 100>(Wbig[L] + 50 * 100, wbuf, tid);
        __syncthreads();
        gemv1<50, 52>(wbuf, act + 50 * THREADS, acc, tid);
        __syncthreads();
        store_act<52, true>(acc, act, tid);
    }

    // ================= layer 4: 100 -> 52pad (true 50), K chunked =================
    stage<50, 52, 50>(W4, wbuf, tid);
    stage_bias<52, 50>(B4, bbuf, tid);
    __syncthreads();
    {
        ull acc[26];
        init_acc<26>(bbuf, acc);
        gemv1<50, 26>(wbuf, act, acc, tid);
        __syncthreads();
        stage<50, 52, 50>(W4 + 50 * 50, wbuf, tid);
        __syncthreads();
        gemv1<50, 26>(wbuf, act + 50 * THREADS, acc, tid);
        __syncthreads();
        store_act<26, true>(acc, act, tid);
    }

    // ================= layer 5: 50 -> 16pad (true 10), keep in regs =================
    stage<50, 16, 10>(W5, wbuf, tid);
    stage_bias<16, 10>(B5, bbuf, tid);
    __syncthreads();
    float g[10];
    {
        ull acc[8];
        init_acc<8>(bbuf, acc);
        gemv1<50, 8>(wbuf, act, acc, tid);
#pragma unroll
        for (int j = 0; j < 5; ++j)
            unpack2(acc[j], g[2 * j], g[2 * j + 1]);
    }

    // ================= epilogue =================
    finish_elem(Sg, Wg, g, b, bb, Btot, out);
}

extern "C" void kernel_launch(void* const* d_in, const int* in_sizes, int n_in,
                              void* d_out, int out_size)
{
    const float* s  = (const float*)d_in[0];
    const float* w  = (const float*)d_in[1];
    const float* W0 = (const float*)d_in[2];
    const float* B0 = (const float*)d_in[3];
    const float* W1 = (const float*)d_in[4];
    const float* B1 = (const float*)d_in[5];
    const float* W2 = (const float*)d_in[6];
    const float* B2 = (const float*)d_in[7];
    const float* W3 = (const float*)d_in[8];
    const float* B3 = (const float*)d_in[9];
    const float* W4 = (const float*)d_in[10];
    const float* B4 = (const float*)d_in[11];
    const float* W5 = (const float*)d_in[12];
    const float* B5 = (const float*)d_in[13];
    float* out = (float*)d_out;

    int Btot = in_sizes[0] / 9;
    int smem_bytes = SMEM_FLOATS * (int)sizeof(float);
    cudaFuncSetAttribute(tbnn_kernel, cudaFuncAttributeMaxDynamicSharedMemorySize, smem_bytes);

    int blocks = (Btot + THREADS - 1) / THREADS;
    tbnn_kernel<<<blocks, THREADS, smem_bytes>>>(
        s, w, W0, B0, W1, B1, W2, B2, W3, B3, W4, B4, W5, B5, out, Btot);
}

// round 6
// speedup vs baseline: 2.0331x; 1.8521x over previous
#include <cuda_runtime.h>
#include <cuda_bf16.h>
#include <math.h>
#include <stdint.h>

#define TPB 256

// ---- smem byte offsets ----
#define SO_BIAS 0        // 112 f32 (448 B)
#define SO_G32  512      // 128 x 16 f32 (8192 B)
#define SO_AH   8704     // act hi: 128 rows x 240 B
#define SO_AL   39424    // act lo
#define SO_WB   70144    // weights hi+lo (max 53760 B)
#define SMEM_BYTES 123904
#define A_LO_OFF 30720   // SO_AL - SO_AH

// ---- device-global weight image (prep output) ----
// per layer: [hi: N8 rows x 120 bf16][lo: same]; rows = n (output), cols = k (input)
__device__ __align__(16) __nv_bfloat16 g_wblob[115200];
__device__ __align__(16) float g_biasblob[672];   // 6 x 112

// ---- PTX helpers ----
__device__ __forceinline__ uint32_t smem_u32(const void* p) {
    uint32_t a;
    asm("{ .reg .u64 t; cvta.to.shared.u64 t, %1; cvt.u32.u64 %0, t; }" : "=r"(a) : "l"(p));
    return a;
}
__device__ __forceinline__ uint32_t lds32(uint32_t a) {
    uint32_t v; asm volatile("ld.shared.b32 %0, [%1];" : "=r"(v) : "r"(a)); return v;
}
__device__ __forceinline__ float2 ldsf2(uint32_t a) {
    float2 v; asm volatile("ld.shared.v2.f32 {%0,%1}, [%2];" : "=f"(v.x), "=f"(v.y) : "r"(a)); return v;
}
__device__ __forceinline__ void sts32(uint32_t a, uint32_t v) {
    asm volatile("st.shared.b32 [%0], %1;" :: "r"(a), "r"(v) : "memory");
}
__device__ __forceinline__ void stsf2(uint32_t a, float x, float y) {
    asm volatile("st.shared.v2.f32 [%0], {%1,%2};" :: "r"(a), "f"(x), "f"(y) : "memory");
}
__device__ __forceinline__ void sts128(uint32_t a, uint32_t x, uint32_t y, uint32_t z, uint32_t w) {
    asm volatile("st.shared.v4.b32 [%0], {%1,%2,%3,%4};" :: "r"(a), "r"(x), "r"(y), "r"(z), "r"(w) : "memory");
}
__device__ __forceinline__ void hmma(float& c0, float& c1, float& c2, float& c3,
                                     uint32_t a0, uint32_t a1, uint32_t a2, uint32_t a3,
                                     uint32_t b0, uint32_t b1) {
    asm volatile(
        "mma.sync.aligned.m16n8k16.row.col.f32.bf16.bf16.f32 "
        "{%0,%1,%2,%3}, {%4,%5,%6,%7}, {%8,%9}, {%0,%1,%2,%3};"
        : "+f"(c0), "+f"(c1), "+f"(c2), "+f"(c3)
        : "r"(a0), "r"(a1), "r"(a2), "r"(a3), "r"(b0), "r"(b1));
}
__device__ __forceinline__ uint32_t pack_hi(float v0, float v1, float& r0, float& r1) {
    __nv_bfloat16 h0 = __float2bfloat16_rn(v0), h1 = __float2bfloat16_rn(v1);
    r0 = v0 - __bfloat162float(h0);
    r1 = v1 - __bfloat162float(h1);
    return (uint32_t)__bfloat16_as_ushort(h0) | ((uint32_t)__bfloat16_as_ushort(h1) << 16);
}
__device__ __forceinline__ uint32_t pack_lo(float r0, float r1) {
    __nv_bfloat16 l0 = __float2bfloat16_rn(r0), l1 = __float2bfloat16_rn(r1);
    return (uint32_t)__bfloat16_as_ushort(l0) | ((uint32_t)__bfloat16_as_ushort(l1) << 16);
}

// ---- 3x3 helpers ----
__device__ __forceinline__ void mm3(const float* a, const float* b, float* c) {
#pragma unroll
    for (int r = 0; r < 3; ++r)
#pragma unroll
        for (int k = 0; k < 3; ++k)
            c[r * 3 + k] = a[r * 3 + 0] * b[0 * 3 + k]
                         + a[r * 3 + 1] * b[1 * 3 + k]
                         + a[r * 3 + 2] * b[2 * 3 + k];
}
__device__ __forceinline__ float tr3(const float* a) { return a[0] + a[4] + a[8]; }
__device__ __forceinline__ float trAB(const float* a, const float* b) {
    float t = 0.f;
#pragma unroll
    for (int i = 0; i < 3; ++i)
#pragma unroll
        for (int k = 0; k < 3; ++k)
            t += a[i * 3 + k] * b[k * 3 + i];
    return t;
}
__device__ __forceinline__ void axpy9(float* acc, float g, const float* m) {
#pragma unroll
    for (int k = 0; k < 9; ++k) acc[k] += g * m[k];
}
__device__ __forceinline__ void axmy9(float* acc, float g, const float* m, const float* n) {
#pragma unroll
    for (int k = 0; k < 9; ++k) acc[k] += g * (m[k] - n[k]);
}

__device__ __forceinline__ void finish_elem(const float* __restrict__ Sg,
                                            const float* __restrict__ Wg,
                                            const float* g, long b, long bb,
                                            int Btot, float* __restrict__ out)
{
    float s[9], w[9];
#pragma unroll
    for (int k = 0; k < 9; ++k) { s[k] = Sg[bb * 9 + k]; w[k] = Wg[bb * 9 + k]; }
    float raw[9];
#pragma unroll
    for (int k = 0; k < 9; ++k) raw[k] = 0.f;

    axpy9(raw, g[0], s);
    float s2[9], w2[9];
    mm3(s, s, s2); mm3(w, w, w2);
    axpy9(raw, g[2], s2);
    { float c = g[2] * tr3(s2) * (1.f / 3.f); raw[0] -= c; raw[4] -= c; raw[8] -= c; }
    axpy9(raw, g[3], w2);
    { float c = g[3] * tr3(w2) * (1.f / 3.f); raw[0] -= c; raw[4] -= c; raw[8] -= c; }
    float sw[9], ws[9];
    mm3(s, w, sw); mm3(w, s, ws);
    axmy9(raw, g[1], sw, ws);
    float tA[9], tB[9];
    mm3(ws, w2, tA); mm3(w2, sw, tB); axmy9(raw, g[6], tA, tB);
    mm3(sw, s2, tA); mm3(s2, ws, tB); axmy9(raw, g[7], tA, tB);
    float ws2[9], s2w[9];
    mm3(w, s2, ws2); mm3(s2, w, s2w);
    axmy9(raw, g[4], ws2, s2w);
    mm3(ws2, w2, tA); mm3(w2, s2w, tB); axmy9(raw, g[9], tA, tB);
    mm3(w2, s, tA); mm3(s, w2, tB);
    axpy9(raw, g[5], tA); axpy9(raw, g[5], tB);
    { float c = g[5] * (2.f / 3.f) * tr3(tB); raw[0] -= c; raw[4] -= c; raw[8] -= c; }
    mm3(w2, s2, tA); mm3(s2, w2, tB);
    axpy9(raw, g[8], tA); axpy9(raw, g[8], tB);
    { float c = g[8] * (2.f / 3.f) * tr3(tB); raw[0] -= c; raw[4] -= c; raw[8] -= c; }

    float Q[9];
#pragma unroll
    for (int k = 0; k < 9; ++k) Q[k] = raw[k];
    { float c = (raw[0] + raw[4] + raw[8]) * (1.f / 3.f); Q[0] -= c; Q[4] -= c; Q[8] -= c; }
    float Qs[9];
#pragma unroll
    for (int r = 0; r < 3; ++r)
#pragma unroll
        for (int c = 0; c < 3; ++c)
            Qs[r * 3 + c] = 0.5f * (Q[r * 3 + c] + Q[c * 3 + r]);
    float ns = 0.f;
#pragma unroll
    for (int k = 0; k < 9; ++k) ns += Qs[k] * Qs[k];
    float invn = 1.0f / sqrtf(ns + 1e-16f);
    if (b < Btot) {
        float* outQ = out + b * 9;
        float* outR = out + (size_t)Btot * 9 + b * 9;
#pragma unroll
        for (int k = 0; k < 9; ++k) { outQ[k] = Qs[k] * invn; outR[k] = raw[k]; }
    }
}

// ================= prep kernel: W -> transposed padded bf16 hi/lo ============
__global__ void prep_kernel(const float* W0, const float* W1, const float* W2,
                            const float* W3, const float* W4, const float* W5,
                            const float* B0, const float* B1, const float* B2,
                            const float* B3, const float* B4, const float* B5)
{
    const float* Ws[6] = {W0, W1, W2, W3, W4, W5};
    const float* Bs[6] = {B0, B1, B2, B3, B4, B5};
    const int Kt[6] = {5, 50, 100, 100, 100, 50};
    const int Nt[6] = {50, 100, 100, 100, 50, 10};
    const int N8[6] = {64, 112, 112, 112, 64, 16};
    const int HB[6] = {0, 15360, 42240, 69120, 96000, 111360};
    const int CUM[7] = {0, 7680, 21120, 34560, 48000, 55680, 57600}; // hi elems

    int idx = blockIdx.x * blockDim.x + threadIdx.x;
    int stride = gridDim.x * blockDim.x;
    for (int i = idx; i < 57600; i += stride) {
        int l = 0;
#pragma unroll
        for (int q = 1; q < 6; ++q) if (i >= CUM[q]) l = q;
        int rem = i - CUM[l];
        int n = rem / 120, k = rem - n * 120;
        float v = (n < Nt[l] && k < Kt[l]) ? Ws[l][k * Nt[l] + n] : 0.f;
        __nv_bfloat16 hi = __float2bfloat16_rn(v);
        __nv_bfloat16 lo = __float2bfloat16_rn(v - __bfloat162float(hi));
        g_wblob[HB[l] + n * 120 + k] = hi;
        g_wblob[HB[l] + N8[l] * 120 + n * 120 + k] = lo;
    }
    for (int j = idx; j < 672; j += stride) {
        int l = j / 112, n = j - l * 112;
        g_biasblob[j] = (n < Nt[l]) ? Bs[l][n] : 0.f;
    }
}

// ================= one MLP layer via mma.sync =================
// KS = k-steps of 16, NT = n-tiles of 8 (NT*8 outputs incl. zero padding)
template <int KS, int NT, bool LAST>
__device__ __forceinline__ void layer_mma(uint32_t sb, int lane, int mbase)
{
    const uint32_t aoff = sb + SO_AH + (uint32_t)(mbase + (lane >> 2)) * 240u
                        + (uint32_t)(lane & 3) * 4u;
    uint32_t ah[KS][4], al[KS][4];
#pragma unroll
    for (int k = 0; k < KS; ++k) {
        ah[k][0] = lds32(aoff + k * 32);
        ah[k][1] = lds32(aoff + k * 32 + 1920);        // row + 8
        ah[k][2] = lds32(aoff + k * 32 + 16);          // k + 8
        ah[k][3] = lds32(aoff + k * 32 + 1920 + 16);
        al[k][0] = lds32(aoff + A_LO_OFF + k * 32);
        al[k][1] = lds32(aoff + A_LO_OFF + k * 32 + 1920);
        al[k][2] = lds32(aoff + A_LO_OFF + k * 32 + 16);
        al[k][3] = lds32(aoff + A_LO_OFF + k * 32 + 1920 + 16);
    }
    const uint32_t wbase = sb + SO_WB + (uint32_t)(lane >> 2) * 240u
                         + (uint32_t)(lane & 3) * 4u;
    const uint32_t wlo = (uint32_t)NT * 8u * 240u;
    const uint32_t arow = sb + SO_AH + (uint32_t)(mbase + (lane >> 2)) * 240u;
    const uint32_t grow = sb + SO_G32 + (uint32_t)(mbase + (lane >> 2)) * 64u;

#pragma unroll 2
    for (int nt = 0; nt < NT; ++nt) {
        float c0 = 0.f, c1 = 0.f, c2 = 0.f, c3 = 0.f;
        const uint32_t wb = wbase + (uint32_t)nt * 1920u;
#pragma unroll
        for (int k = 0; k < KS; ++k) {
            uint32_t bh0 = lds32(wb + k * 32), bh1 = lds32(wb + k * 32 + 16);
            uint32_t bl0 = lds32(wb + wlo + k * 32), bl1 = lds32(wb + wlo + k * 32 + 16);
            hmma(c0, c1, c2, c3, ah[k][0], ah[k][1], ah[k][2], ah[k][3], bh0, bh1);
            hmma(c0, c1, c2, c3, ah[k][0], ah[k][1], ah[k][2], ah[k][3], bl0, bl1);
            hmma(c0, c1, c2, c3, al[k][0], al[k][1], al[k][2], al[k][3], bh0, bh1);
        }
        const int col0 = nt * 8 + 2 * (lane & 3);
        float2 bp = ldsf2(sb + SO_BIAS + (uint32_t)col0 * 4u);
        float v0 = c0 + bp.x, v1 = c1 + bp.y;
        float v2 = c2 + bp.x, v3 = c3 + bp.y;
        if (!LAST) {
            v0 = fmaxf(v0, 0.1f * v0); v1 = fmaxf(v1, 0.1f * v1);
            v2 = fmaxf(v2, 0.1f * v2); v3 = fmaxf(v3, 0.1f * v3);
            float r0, r1, r2, r3;
            uint32_t h01 = pack_hi(v0, v1, r0, r1);
            uint32_t h23 = pack_hi(v2, v3, r2, r3);
            sts32(arow + (uint32_t)col0 * 2u, h01);
            sts32(arow + 1920u + (uint32_t)col0 * 2u, h23);
            sts32(arow + A_LO_OFF + (uint32_t)col0 * 2u, pack_lo(r0, r1));
            sts32(arow + A_LO_OFF + 1920u + (uint32_t)col0 * 2u, pack_lo(r2, r3));
        } else {
            stsf2(grow + (uint32_t)col0 * 4u, v0, v1);
            stsf2(grow + 512u + (uint32_t)col0 * 4u, v2, v3);   // row + 8
        }
    }
    __syncwarp();
}

// ================= main kernel =================
__global__ void __launch_bounds__(TPB, 1) tbnn_hmma_kernel(
    const float* __restrict__ Sg, const float* __restrict__ Wg,
    float* __restrict__ out, int Btot)
{
    extern __shared__ char smemc[];
    const uint32_t sb = smem_u32(smemc);

    const int tid = threadIdx.x;
    const int lane = tid & 31;
    const int wid = tid >> 5;
    const int mbase = wid * 16;     // this warp's 16 rows
    const long blkbase = (long)blockIdx.x * 128;

    // ---- prologue: invariants -> act rows (threads 0..127) ----
    if (tid < 128) {
        const long b = blkbase + tid;
        const long bb = (b < Btot) ? b : (long)Btot - 1;
        float s[9], w[9];
#pragma unroll
        for (int k = 0; k < 9; ++k) { s[k] = Sg[bb * 9 + k]; w[k] = Wg[bb * 9 + k]; }
        float s2[9], w2[9];
        mm3(s, s, s2); mm3(w, w, w2);
        float inv[6];
        inv[0] = tr3(s2); inv[1] = tr3(w2); inv[2] = trAB(s2, s);
        inv[3] = trAB(w2, s); inv[4] = trAB(w2, s2); inv[5] = 0.f;

        uint32_t hw[8], lw[8];
#pragma unroll
        for (int j = 0; j < 8; ++j) { hw[j] = 0u; lw[j] = 0u; }
#pragma unroll
        for (int j = 0; j < 3; ++j) {
            float r0, r1;
            hw[j] = pack_hi(inv[2 * j], inv[2 * j + 1], r0, r1);
            lw[j] = pack_lo(r0, r1);
        }
        const uint32_t ra = sb + SO_AH + (uint32_t)tid * 240u;
        sts128(ra, hw[0], hw[1], hw[2], hw[3]);
        sts128(ra + 16u, hw[4], hw[5], hw[6], hw[7]);
        sts128(ra + A_LO_OFF, lw[0], lw[1], lw[2], lw[3]);
        sts128(ra + A_LO_OFF + 16u, lw[4], lw[5], lw[6], lw[7]);
    }

    // ---- per-layer: stage weights then MMA ----
    const int N16[6] = {1920, 3360, 3360, 3360, 1920, 480};  // uint4 per layer (hi+lo)
    const int HB[6]  = {0, 15360, 42240, 69120, 96000, 111360};

#pragma unroll
    for (int l = 0; l < 6; ++l) {
        __syncthreads();   // prev layer done reading wbuf (and prologue visible)
        {
            const uint4* src = reinterpret_cast<const uint4*>(g_wblob + HB[l]);
            uint4* dst = reinterpret_cast<uint4*>(smemc + SO_WB);
            const int n16 = N16[l];
            for (int i = tid; i < n16; i += TPB) dst[i] = src[i];
            float* bs = reinterpret_cast<float*>(smemc + SO_BIAS);
            for (int j = tid; j < 112; j += TPB) bs[j] = g_biasblob[l * 112 + j];
        }
        __syncthreads();   // staged weights visible

        if (l == 0)      layer_mma<1, 8,  false>(sb, lane, mbase);
        else if (l == 1) layer_mma<4, 14, false>(sb, lane, mbase);
        else if (l == 2) layer_mma<7, 14, false>(sb, lane, mbase);
        else if (l == 3) layer_mma<7, 14, false>(sb, lane, mbase);
        else if (l == 4) layer_mma<7, 8,  false>(sb, lane, mbase);
        else             layer_mma<4, 2,  true >(sb, lane, mbase);
    }
    __syncthreads();   // g32 visible across warps

    // ---- epilogue: one element per thread (threads 0..127) ----
    if (tid < 128) {
        const long b = blkbase + tid;
        const long bb = (b < Btot) ? b : (long)Btot - 1;
        const float* gp = reinterpret_cast<const float*>(smemc + SO_G32) + tid * 16;
        float g[10];
#pragma unroll
        for (int n = 0; n < 10; ++n) g[n] = gp[n];
        finish_elem(Sg, Wg, g, b, bb, Btot, out);
    }
}

// ================= launch =================
extern "C" void kernel_launch(void* const* d_in, const int* in_sizes, int n_in,
                              void* d_out, int out_size)
{
    const float* s  = (const float*)d_in[0];
    const float* w  = (const float*)d_in[1];
    const float* W0 = (const float*)d_in[2];
    const float* B0 = (const float*)d_in[3];
    const float* W1 = (const float*)d_in[4];
    const float* B1 = (const float*)d_in[5];
    const float* W2 = (const float*)d_in[6];
    const float* B2 = (const float*)d_in[7];
    const float* W3 = (const float*)d_in[8];
    const float* B3 = (const float*)d_in[9];
    const float* W4 = (const float*)d_in[10];
    const float* B4 = (const float*)d_in[11];
    const float* W5 = (const float*)d_in[12];
    const float* B5 = (const float*)d_in[13];
    float* out = (float*)d_out;

    int Btot = in_sizes[0] / 9;

    prep_kernel<<<64, 256>>>(W0, W1, W2, W3, W4, W5, B0, B1, B2, B3, B4, B5);

    cudaFuncSetAttribute(tbnn_hmma_kernel,
                         cudaFuncAttributeMaxDynamicSharedMemorySize, SMEM_BYTES);
    int blocks = (Btot + 127) / 128;
    tbnn_hmma_kernel<<<blocks, TPB, SMEM_BYTES>>>(s, w, out, Btot);
}

// round 7
// speedup vs baseline: 3.0155x; 1.4832x over previous
#include <cuda_runtime.h>
#include <cuda_bf16.h>
#include <math.h>
#include <stdint.h>

#define TPB 256

// ---- smem byte offsets ----
#define SO_BIAS 0        // 112 f32 (448 B)
#define SO_G32  512      // 8192 B: layer-0 act staging, later g output
#define SO_WB   8704     // weights, max 50176 B
#define SMEM_BYTES 58880

// ---- device-global weight image (prep output) ----
// per (layer, nt, kk, lane): uint4 {b0h, b1h, b0l, b1l}
__device__ __align__(16) uint4 g_wblob4[10368];
__device__ __align__(16) float g_biasblob[672];   // 6 x 112

// ---- PTX helpers ----
__device__ __forceinline__ uint32_t smem_u32(const void* p) {
    uint32_t a;
    asm("{ .reg .u64 t; cvta.to.shared.u64 t, %1; cvt.u32.u64 %0, t; }" : "=r"(a) : "l"(p));
    return a;
}
__device__ __forceinline__ uint32_t lds32(uint32_t a) {
    uint32_t v; asm volatile("ld.shared.b32 %0, [%1];" : "=r"(v) : "r"(a)); return v;
}
__device__ __forceinline__ uint4 lds128(uint32_t a) {
    uint4 v;
    asm volatile("ld.shared.v4.b32 {%0,%1,%2,%3}, [%4];"
                 : "=r"(v.x), "=r"(v.y), "=r"(v.z), "=r"(v.w) : "r"(a));
    return v;
}
__device__ __forceinline__ float2 ldsf2(uint32_t a) {
    float2 v; asm volatile("ld.shared.v2.f32 {%0,%1}, [%2];" : "=f"(v.x), "=f"(v.y) : "r"(a)); return v;
}
__device__ __forceinline__ void stsf2(uint32_t a, float x, float y) {
    asm volatile("st.shared.v2.f32 [%0], {%1,%2};" :: "r"(a), "f"(x), "f"(y) : "memory");
}
__device__ __forceinline__ void sts128(uint32_t a, uint32_t x, uint32_t y, uint32_t z, uint32_t w) {
    asm volatile("st.shared.v4.b32 [%0], {%1,%2,%3,%4};" :: "r"(a), "r"(x), "r"(y), "r"(z), "r"(w) : "memory");
}
__device__ __forceinline__ void hmma(float& c0, float& c1, float& c2, float& c3,
                                     uint32_t a0, uint32_t a1, uint32_t a2, uint32_t a3,
                                     uint32_t b0, uint32_t b1) {
    asm volatile(
        "mma.sync.aligned.m16n8k16.row.col.f32.bf16.bf16.f32 "
        "{%0,%1,%2,%3}, {%4,%5,%6,%7}, {%8,%9}, {%0,%1,%2,%3};"
        : "+f"(c0), "+f"(c1), "+f"(c2), "+f"(c3)
        : "r"(a0), "r"(a1), "r"(a2), "r"(a3), "r"(b0), "r"(b1));
}
__device__ __forceinline__ uint32_t pack_hi(float v0, float v1, float& r0, float& r1) {
    __nv_bfloat16 h0 = __float2bfloat16_rn(v0), h1 = __float2bfloat16_rn(v1);
    r0 = v0 - __bfloat162float(h0);
    r1 = v1 - __bfloat162float(h1);
    return (uint32_t)__bfloat16_as_ushort(h0) | ((uint32_t)__bfloat16_as_ushort(h1) << 16);
}
__device__ __forceinline__ uint32_t pack_lo(float r0, float r1) {
    __nv_bfloat16 l0 = __float2bfloat16_rn(r0), l1 = __float2bfloat16_rn(r1);
    return (uint32_t)__bfloat16_as_ushort(l0) | ((uint32_t)__bfloat16_as_ushort(l1) << 16);
}

// ---- 3x3 helpers ----
__device__ __forceinline__ void mm3(const float* a, const float* b, float* c) {
#pragma unroll
    for (int r = 0; r < 3; ++r)
#pragma unroll
        for (int k = 0; k < 3; ++k)
            c[r * 3 + k] = a[r * 3 + 0] * b[0 * 3 + k]
                         + a[r * 3 + 1] * b[1 * 3 + k]
                         + a[r * 3 + 2] * b[2 * 3 + k];
}
__device__ __forceinline__ float tr3(const float* a) { return a[0] + a[4] + a[8]; }
__device__ __forceinline__ float trAB(const float* a, const float* b) {
    float t = 0.f;
#pragma unroll
    for (int i = 0; i < 3; ++i)
#pragma unroll
        for (int k = 0; k < 3; ++k)
            t += a[i * 3 + k] * b[k * 3 + i];
    return t;
}
__device__ __forceinline__ void axpy9(float* acc, float g, const float* m) {
#pragma unroll
    for (int k = 0; k < 9; ++k) acc[k] += g * m[k];
}
__device__ __forceinline__ void axmy9(float* acc, float g, const float* m, const float* n) {
#pragma unroll
    for (int k = 0; k < 9; ++k) acc[k] += g * (m[k] - n[k]);
}

__device__ __forceinline__ void finish_elem(const float* __restrict__ Sg,
                                            const float* __restrict__ Wg,
                                            const float* g, long b, long bb,
                                            int Btot, float* __restrict__ out)
{
    float s[9], w[9];
#pragma unroll
    for (int k = 0; k < 9; ++k) { s[k] = Sg[bb * 9 + k]; w[k] = Wg[bb * 9 + k]; }
    float raw[9];
#pragma unroll
    for (int k = 0; k < 9; ++k) raw[k] = 0.f;

    axpy9(raw, g[0], s);
    float s2[9], w2[9];
    mm3(s, s, s2); mm3(w, w, w2);
    axpy9(raw, g[2], s2);
    { float c = g[2] * tr3(s2) * (1.f / 3.f); raw[0] -= c; raw[4] -= c; raw[8] -= c; }
    axpy9(raw, g[3], w2);
    { float c = g[3] * tr3(w2) * (1.f / 3.f); raw[0] -= c; raw[4] -= c; raw[8] -= c; }
    float sw[9], ws[9];
    mm3(s, w, sw); mm3(w, s, ws);
    axmy9(raw, g[1], sw, ws);
    float tA[9], tB[9];
    mm3(ws, w2, tA); mm3(w2, sw, tB); axmy9(raw, g[6], tA, tB);
    mm3(sw, s2, tA); mm3(s2, ws, tB); axmy9(raw, g[7], tA, tB);
    float ws2[9], s2w[9];
    mm3(w, s2, ws2); mm3(s2, w, s2w);
    axmy9(raw, g[4], ws2, s2w);
    mm3(ws2, w2, tA); mm3(w2, s2w, tB); axmy9(raw, g[9], tA, tB);
    mm3(w2, s, tA); mm3(s, w2, tB);
    axpy9(raw, g[5], tA); axpy9(raw, g[5], tB);
    { float c = g[5] * (2.f / 3.f) * tr3(tB); raw[0] -= c; raw[4] -= c; raw[8] -= c; }
    mm3(w2, s2, tA); mm3(s2, w2, tB);
    axpy9(raw, g[8], tA); axpy9(raw, g[8], tB);
    { float c = g[8] * (2.f / 3.f) * tr3(tB); raw[0] -= c; raw[4] -= c; raw[8] -= c; }

    float Q[9];
#pragma unroll
    for (int k = 0; k < 9; ++k) Q[k] = raw[k];
    { float c = (raw[0] + raw[4] + raw[8]) * (1.f / 3.f); Q[0] -= c; Q[4] -= c; Q[8] -= c; }
    float Qs[9];
#pragma unroll
    for (int r = 0; r < 3; ++r)
#pragma unroll
        for (int c = 0; c < 3; ++c)
            Qs[r * 3 + c] = 0.5f * (Q[r * 3 + c] + Q[c * 3 + r]);
    float ns = 0.f;
#pragma unroll
    for (int k = 0; k < 9; ++k) ns += Qs[k] * Qs[k];
    float invn = 1.0f / sqrtf(ns + 1e-16f);
    if (b < Btot) {
        float* outQ = out + b * 9;
        float* outR = out + (size_t)Btot * 9 + b * 9;
#pragma unroll
        for (int k = 0; k < 9; ++k) { outQ[k] = Qs[k] * invn; outR[k] = raw[k]; }
    }
}

// ================= prep kernel: W -> per-lane B-fragment blob ================
__global__ void prep_kernel(const float* W0, const float* W1, const float* W2,
                            const float* W3, const float* W4, const float* W5,
                            const float* B0, const float* B1, const float* B2,
                            const float* B3, const float* B4, const float* B5)
{
    const float* Ws[6] = {W0, W1, W2, W3, W4, W5};
    const float* Bs[6] = {B0, B1, B2, B3, B4, B5};
    const int Kt[6]  = {5, 50, 100, 100, 100, 50};
    const int Nt[6]  = {50, 100, 100, 100, 50, 10};
    const int KSt[6] = {1, 4, 7, 7, 7, 4};
    const int OFF[7] = {0, 256, 2048, 5184, 8320, 10112, 10368};

    int idx = blockIdx.x * blockDim.x + threadIdx.x;
    int stride = gridDim.x * blockDim.x;
    for (int i = idx; i < 10368; i += stride) {
        int l = 0;
#pragma unroll
        for (int q = 1; q < 6; ++q) if (i >= OFF[q]) l = q;
        int rem = i - OFF[l];
        int lane = rem & 31;
        int q2 = rem >> 5;
        int kk = q2 % KSt[l];
        int nt = q2 / KSt[l];
        int n = nt * 8 + (lane >> 2);
        int k0 = kk * 16 + 2 * (lane & 3);

        float f[4];
#pragma unroll
        for (int e = 0; e < 2; ++e) {
            int k = k0 + 8 * e;
            f[2 * e + 0] = (k < Kt[l] && n < Nt[l]) ? Ws[l][k * Nt[l] + n] : 0.f;
            f[2 * e + 1] = (k + 1 < Kt[l] && n < Nt[l]) ? Ws[l][(k + 1) * Nt[l] + n] : 0.f;
        }
        __nv_bfloat16 h[4], lo[4];
#pragma unroll
        for (int e = 0; e < 4; ++e) {
            h[e] = __float2bfloat16_rn(f[e]);
            lo[e] = __float2bfloat16_rn(f[e] - __bfloat162float(h[e]));
        }
        uint4 v;
        v.x = (uint32_t)__bfloat16_as_ushort(h[0]) | ((uint32_t)__bfloat16_as_ushort(h[1]) << 16);
        v.y = (uint32_t)__bfloat16_as_ushort(h[2]) | ((uint32_t)__bfloat16_as_ushort(h[3]) << 16);
        v.z = (uint32_t)__bfloat16_as_ushort(lo[0]) | ((uint32_t)__bfloat16_as_ushort(lo[1]) << 16);
        v.w = (uint32_t)__bfloat16_as_ushort(lo[2]) | ((uint32_t)__bfloat16_as_ushort(lo[3]) << 16);
        g_wblob4[i] = v;
    }
    for (int j = idx; j < 672; j += stride) {
        int l = j / 112, n = j - l * 112;
        g_biasblob[j] = (n < Nt[l]) ? Bs[l][n] : 0.f;
    }
}

// ================= one MLP layer: A in regs, B frags 1 x LDS.128 =============
// KS k-steps (input), NT n-tiles (output, even). Writes next A frags nh/nl.
template <int KS, int NT, bool LAST>
__device__ __forceinline__ void layer_mma(
    uint32_t sb, int lane, int mbase,
    const uint32_t (*ah)[4], const uint32_t (*al)[4],
    uint32_t (*nh)[4], uint32_t (*nl)[4])
{
    const uint32_t wb = sb + SO_WB + (uint32_t)lane * 16u;
    const uint32_t brow = sb + SO_BIAS;

#pragma unroll
    for (int nt = 0; nt < NT; nt += 2) {
        float c0 = 0.f, c1 = 0.f, c2 = 0.f, c3 = 0.f;
        float d0 = 0.f, d1 = 0.f, d2 = 0.f, d3 = 0.f;
        const uint32_t w0 = wb + (uint32_t)(nt * KS) * 512u;
        const uint32_t w1 = wb + (uint32_t)((nt + 1) * KS) * 512u;
#pragma unroll
        for (int kk = 0; kk < KS; ++kk) {
            uint4 wv0 = lds128(w0 + (uint32_t)kk * 512u);
            uint4 wv1 = lds128(w1 + (uint32_t)kk * 512u);
            hmma(c0, c1, c2, c3, ah[kk][0], ah[kk][1], ah[kk][2], ah[kk][3], wv0.x, wv0.y);
            hmma(d0, d1, d2, d3, ah[kk][0], ah[kk][1], ah[kk][2], ah[kk][3], wv1.x, wv1.y);
            hmma(c0, c1, c2, c3, ah[kk][0], ah[kk][1], ah[kk][2], ah[kk][3], wv0.z, wv0.w);
            hmma(d0, d1, d2, d3, ah[kk][0], ah[kk][1], ah[kk][2], ah[kk][3], wv1.z, wv1.w);
            hmma(c0, c1, c2, c3, al[kk][0], al[kk][1], al[kk][2], al[kk][3], wv0.x, wv0.y);
            hmma(d0, d1, d2, d3, al[kk][0], al[kk][1], al[kk][2], al[kk][3], wv1.x, wv1.y);
        }
        const int col0 = nt * 8 + 2 * (lane & 3);
        float2 bp0 = ldsf2(brow + (uint32_t)col0 * 4u);
        float2 bp1 = ldsf2(brow + (uint32_t)(col0 + 8) * 4u);
        float v0 = c0 + bp0.x, v1 = c1 + bp0.y, v2 = c2 + bp0.x, v3 = c3 + bp0.y;
        float u0 = d0 + bp1.x, u1 = d1 + bp1.y, u2 = d2 + bp1.x, u3 = d3 + bp1.y;
        if (!LAST) {
            v0 = fmaxf(v0, 0.1f * v0); v1 = fmaxf(v1, 0.1f * v1);
            v2 = fmaxf(v2, 0.1f * v2); v3 = fmaxf(v3, 0.1f * v3);
            u0 = fmaxf(u0, 0.1f * u0); u1 = fmaxf(u1, 0.1f * u1);
            u2 = fmaxf(u2, 0.1f * u2); u3 = fmaxf(u3, 0.1f * u3);
            const int kk2 = nt >> 1;
            float r0, r1;
            nh[kk2][0] = pack_hi(v0, v1, r0, r1); nl[kk2][0] = pack_lo(r0, r1);
            nh[kk2][1] = pack_hi(v2, v3, r0, r1); nl[kk2][1] = pack_lo(r0, r1);
            nh[kk2][2] = pack_hi(u0, u1, r0, r1); nl[kk2][2] = pack_lo(r0, r1);
            nh[kk2][3] = pack_hi(u2, u3, r0, r1); nl[kk2][3] = pack_lo(r0, r1);
        } else {
            const uint32_t grow = sb + SO_G32 + (uint32_t)(mbase + (lane >> 2)) * 64u;
            stsf2(grow + (uint32_t)col0 * 4u, v0, v1);
            stsf2(grow + 512u + (uint32_t)col0 * 4u, v2, v3);
            stsf2(grow + (uint32_t)(col0 + 8) * 4u, u0, u1);
            stsf2(grow + 512u + (uint32_t)(col0 + 8) * 4u, u2, u3);
        }
    }
}

// ================= main kernel =================
__global__ void __launch_bounds__(TPB, 1) tbnn_hmma_kernel(
    const float* __restrict__ Sg, const float* __restrict__ Wg,
    float* __restrict__ out, int Btot)
{
    extern __shared__ char smemc[];
    const uint32_t sb = smem_u32(smemc);

    const int tid = threadIdx.x;
    const int lane = tid & 31;
    const int wid = tid >> 5;
    const int mbase = wid * 16;
    const long blkbase = (long)blockIdx.x * 128;

    // ---- prologue: invariants -> layer-0 act staging (reuses g32 area) ----
    if (tid < 128) {
        const long b = blkbase + tid;
        const long bb = (b < Btot) ? b : (long)Btot - 1;
        float s[9], w[9];
#pragma unroll
        for (int k = 0; k < 9; ++k) { s[k] = Sg[bb * 9 + k]; w[k] = Wg[bb * 9 + k]; }
        float s2[9], w2[9];
        mm3(s, s, s2); mm3(w, w, w2);
        float inv[6];
        inv[0] = tr3(s2); inv[1] = tr3(w2); inv[2] = trAB(s2, s);
        inv[3] = trAB(w2, s); inv[4] = trAB(w2, s2); inv[5] = 0.f;

        uint32_t hw[8], lw[8];
#pragma unroll
        for (int j = 0; j < 8; ++j) { hw[j] = 0u; lw[j] = 0u; }
#pragma unroll
        for (int j = 0; j < 3; ++j) {
            float r0, r1;
            hw[j] = pack_hi(inv[2 * j], inv[2 * j + 1], r0, r1);
            lw[j] = pack_lo(r0, r1);
        }
        const uint32_t ra = sb + SO_G32 + (uint32_t)tid * 32u;
        sts128(ra, hw[0], hw[1], hw[2], hw[3]);
        sts128(ra + 16u, hw[4], hw[5], hw[6], hw[7]);
        sts128(ra + 4096u, lw[0], lw[1], lw[2], lw[3]);
        sts128(ra + 4096u + 16u, lw[4], lw[5], lw[6], lw[7]);
    }

    // ---- fragment register files (ping-pong) ----
    uint32_t ahA[7][4], alA[7][4], ahB[7][4], alB[7][4];

    const int N4[6]  = {256, 1792, 3136, 3136, 1792, 256};  // uint4 per layer
    const int OFF[6] = {0, 256, 2048, 5184, 8320, 10112};

#pragma unroll
    for (int l = 0; l < 6; ++l) {
        __syncthreads();   // prev layer wbuf reads done; prologue visible (l=0)
        {
            const uint4* src = g_wblob4 + OFF[l];
            uint4* dst = reinterpret_cast<uint4*>(smemc + SO_WB);
            const int n4 = N4[l];
            for (int i = tid; i < n4; i += TPB) dst[i] = src[i];
            float* bs = reinterpret_cast<float*>(smemc + SO_BIAS);
            for (int j = tid; j < 112; j += TPB) bs[j] = g_biasblob[l * 112 + j];
        }
        __syncthreads();

        if (l == 0) {
            // load layer-0 A frags from staging
            const uint32_t aoff = sb + SO_G32 + (uint32_t)(mbase + (lane >> 2)) * 32u
                                + (uint32_t)(lane & 3) * 4u;
            ahA[0][0] = lds32(aoff);
            ahA[0][1] = lds32(aoff + 256u);
            ahA[0][2] = lds32(aoff + 16u);
            ahA[0][3] = lds32(aoff + 256u + 16u);
            alA[0][0] = lds32(aoff + 4096u);
            alA[0][1] = lds32(aoff + 4096u + 256u);
            alA[0][2] = lds32(aoff + 4096u + 16u);
            alA[0][3] = lds32(aoff + 4096u + 256u + 16u);
            __syncthreads();   // staging reads done before L5 overwrites g32 (safe margin)
            layer_mma<1, 8,  false>(sb, lane, mbase, ahA, alA, ahB, alB);
        }
        else if (l == 1) layer_mma<4, 14, false>(sb, lane, mbase, ahB, alB, ahA, alA);
        else if (l == 2) layer_mma<7, 14, false>(sb, lane, mbase, ahA, alA, ahB, alB);
        else if (l == 3) layer_mma<7, 14, false>(sb, lane, mbase, ahB, alB, ahA, alA);
        else if (l == 4) layer_mma<7, 8,  false>(sb, lane, mbase, ahA, alA, ahB, alB);
        else             layer_mma<4, 2,  true >(sb, lane, mbase, ahB, alB, ahA, alA);
    }
    __syncthreads();   // g32 visible

    // ---- epilogue: one element per thread (threads 0..127) ----
    if (tid < 128) {
        const long b = blkbase + tid;
        const long bb = (b < Btot) ? b : (long)Btot - 1;
        const float* gp = reinterpret_cast<const float*>(smemc + SO_G32) + tid * 16;
        float g[10];
#pragma unroll
        for (int n = 0; n < 10; ++n) g[n] = gp[n];
        finish_elem(Sg, Wg, g, b, bb, Btot, out);
    }
}

// ================= launch =================
extern "C" void kernel_launch(void* const* d_in, const int* in_sizes, int n_in,
                              void* d_out, int out_size)
{
    const float* s  = (const float*)d_in[0];
    const float* w  = (const float*)d_in[1];
    const float* W0 = (const float*)d_in[2];
    const float* B0 = (const float*)d_in[3];
    const float* W1 = (const float*)d_in[4];
    const float* B1 = (const float*)d_in[5];
    const float* W2 = (const float*)d_in[6];
    const float* B2 = (const float*)d_in[7];
    const float* W3 = (const float*)d_in[8];
    const float* B3 = (const float*)d_in[9];
    const float* W4 = (const float*)d_in[10];
    const float* B4 = (const float*)d_in[11];
    const float* W5 = (const float*)d_in[12];
    const float* B5 = (const float*)d_in[13];
    float* out = (float*)d_out;

    int Btot = in_sizes[0] / 9;

    prep_kernel<<<64, 256>>>(W0, W1, W2, W3, W4, W5, B0, B1, B2, B3, B4, B5);

    cudaFuncSetAttribute(tbnn_hmma_kernel,
                         cudaFuncAttributeMaxDynamicSharedMemorySize, SMEM_BYTES);
    int blocks = (Btot + 127) / 128;
    tbnn_hmma_kernel<<<blocks, TPB, SMEM_BYTES>>>(s, w, out, Btot);
}